// round 17
// baseline (speedup 1.0000x reference)
#include <cuda_runtime.h>
#include <cuda_bf16.h>
#include <cuda_fp16.h>
#include <cstdint>

#define Bq 2
#define Sq 2048
#define Rq 128
#define Eq 2048
#define Hq 16
#define Dq 128
#define Lq (Sq + Rq)   // 2176

// ---------------- scratch (device globals, no allocations) ----------------
__device__ __align__(256) int8_t g_x8[(size_t)Bq * Sq * Eq];   // quantized acts int8
__device__ __align__(256) int8_t g_w8[3][(size_t)Eq * Eq];     // ternary weights int8
__device__ __half        g_rt16[(size_t)Bq * Rq * Eq];     // reasoning tokens fp16
__device__ __half        g_kw16[(size_t)Eq * Eq];          // k_w fp16
__device__ __half        g_vw16[(size_t)Eq * Eq];          // v_w fp16
__device__ __half        g_ow16[(size_t)Eq * Eq];          // out_w fp16
__device__ __half        g_o16[(size_t)Bq * Sq * Eq];      // attention output fp16
__device__ __half        g_q16[(size_t)Bq * Sq * Eq];      // Q fp16 (pre-scaled by 1/sqrt(D))
__device__ __half        g_k16[(size_t)Bq * Lq * Eq];      // K fp16
__device__ __half        g_v16[(size_t)Bq * Lq * Eq];      // V fp16 [B,L,E]
__device__ float g_rows[(size_t)Bq * Sq];                  // per-row act scale s
__device__ float g_part[3 * 1024];
__device__ float g_scale[3];

// ---------------- PTX helpers ----------------
typedef unsigned long long ull;
__device__ __forceinline__ uint32_t smem_u32(const void* p) {
    uint32_t a;
    asm("{ .reg .u64 t; cvta.to.shared.u64 t, %1; cvt.u32.u64 %0, t; }" : "=r"(a) : "l"(p));
    return a;
}
__device__ __forceinline__ void ldmx4(uint32_t* r, uint32_t addr) {
    asm volatile("ldmatrix.sync.aligned.m8n8.x4.shared.b16 {%0,%1,%2,%3}, [%4];"
                 : "=r"(r[0]), "=r"(r[1]), "=r"(r[2]), "=r"(r[3]) : "r"(addr));
}
__device__ __forceinline__ void ldmx4t(uint32_t* r, uint32_t addr) {
    asm volatile("ldmatrix.sync.aligned.m8n8.x4.trans.shared.b16 {%0,%1,%2,%3}, [%4];"
                 : "=r"(r[0]), "=r"(r[1]), "=r"(r[2]), "=r"(r[3]) : "r"(addr));
}
__device__ __forceinline__ void mma16816h(float* c, const uint32_t* a, const uint32_t* b) {
    asm volatile("mma.sync.aligned.m16n8k16.row.col.f32.f16.f16.f32 "
                 "{%0,%1,%2,%3}, {%4,%5,%6,%7}, {%8,%9}, {%0,%1,%2,%3};"
                 : "+f"(c[0]), "+f"(c[1]), "+f"(c[2]), "+f"(c[3])
                 : "r"(a[0]), "r"(a[1]), "r"(a[2]), "r"(a[3]), "r"(b[0]), "r"(b[1]));
}
__device__ __forceinline__ void mma16832s8(int* c, const uint32_t* a, const uint32_t* b) {
    asm volatile("mma.sync.aligned.m16n8k32.row.col.s32.s8.s8.s32 "
                 "{%0,%1,%2,%3}, {%4,%5,%6,%7}, {%8,%9}, {%0,%1,%2,%3};"
                 : "+r"(c[0]), "+r"(c[1]), "+r"(c[2]), "+r"(c[3])
                 : "r"(a[0]), "r"(a[1]), "r"(a[2]), "r"(a[3]), "r"(b[0]), "r"(b[1]));
}
__device__ __forceinline__ void cpa16(uint32_t dst, const void* src) {
    asm volatile("cp.async.cg.shared.global [%0], [%1], 16;" :: "r"(dst), "l"(src) : "memory");
}
__device__ __forceinline__ void cpa_commit() {
    asm volatile("cp.async.commit_group;" ::: "memory");
}
__device__ __forceinline__ void cpa_wait0() {
    asm volatile("cp.async.wait_group 0;" ::: "memory");
}
__device__ __forceinline__ void cpa_wait1() {
    asm volatile("cp.async.wait_group 1;" ::: "memory");
}
// smem rows of 64 bytes; 16B group g stored at g ^ ((row>>1)&3)
__device__ __forceinline__ uint32_t swoff(int r, int g) {
    return (uint32_t)(r * 64 + ((g ^ ((r >> 1) & 3)) << 4));
}
// per-lane address offset for B-side ldmatrix.x4 (2 consecutive n-frags of 8 rows)
__device__ __forceinline__ uint32_t boff4(int base_row, int lane) {
    int r = base_row + ((lane >> 4) << 3) + (lane & 7);
    int g = (lane >> 3) & 1;
    return swoff(r, g);
}
__device__ __forceinline__ uint32_t h2pack(float x, float y) {
    __half2 p = __floats2half2_rn(x, y);
    return *(uint32_t*)&p;
}

// ---------------- weight mean(|w|) : stage 1 ----------------
__global__ void reduce_abs_kernel(const float* __restrict__ w0, const float* __restrict__ w1,
                                  const float* __restrict__ w2, float* __restrict__ part) {
    const float* w = (blockIdx.y == 0) ? w0 : ((blockIdx.y == 1) ? w1 : w2);
    int t = threadIdx.x;
    size_t base = (size_t)blockIdx.x * 4096;
    float s = 0.f;
#pragma unroll
    for (int i = 0; i < 16; i++) s += fabsf(w[base + t + i * 256]);
    __shared__ float red[256];
    red[t] = s;
    __syncthreads();
    for (int o = 128; o > 0; o >>= 1) {
        if (t < o) red[t] += red[t + o];
        __syncthreads();
    }
    if (t == 0) part[blockIdx.y * 1024 + blockIdx.x] = red[0];
}

__global__ void finalize_scale_kernel(const float* __restrict__ part, float* __restrict__ scale) {
    int w = blockIdx.x;
    int t = threadIdx.x;
    float s = part[w * 1024 + t] + part[w * 1024 + t + 256] +
              part[w * 1024 + t + 512] + part[w * 1024 + t + 768];
    __shared__ float red[256];
    red[t] = s;
    __syncthreads();
    for (int o = 128; o > 0; o >>= 1) {
        if (t < o) red[t] += red[t + o];
        __syncthreads();
    }
    if (t == 0) {
        float mean = red[0] * (1.0f / ((float)Eq * (float)Eq));
        scale[w] = fmaxf(mean, 1e-5f);
    }
}

// ---------------- merged weight prep ----------------
// wi 0..2: ternary int8 (q/k/v). wi==1: also kw16 fp16. wi==2: also vw16. wi==3: ow16.
__global__ void prep_weights(const float* __restrict__ qw, const float* __restrict__ kw,
                             const float* __restrict__ vw, const float* __restrict__ ow,
                             int8_t* __restrict__ w8,
                             __half* __restrict__ kw16, __half* __restrict__ vw16,
                             __half* __restrict__ ow16,
                             const float* __restrict__ scale) {
    int wi = blockIdx.y;
    const float* w = (wi == 0) ? qw : ((wi == 1) ? kw : ((wi == 2) ? vw : ow));
    float inv = (wi < 3) ? __frcp_rn(scale[wi]) : 0.f;
    size_t e0 = ((size_t)blockIdx.x * 256 + threadIdx.x) * 8;
    int8_t* wo = (wi < 3) ? (w8 + (size_t)wi * Eq * Eq + e0) : nullptr;
    __half* h16 = (wi == 1) ? (kw16 + e0)
                : ((wi == 2) ? (vw16 + e0) : ((wi == 3) ? (ow16 + e0) : nullptr));
    int8_t q8[8];
#pragma unroll
    for (int i = 0; i < 8; i += 4) {
        float4 v = *(const float4*)&w[e0 + i];
        float f[4] = {v.x, v.y, v.z, v.w};
#pragma unroll
        for (int j = 0; j < 4; j++) {
            if (wo) q8[i + j] = (int8_t)(int)(fminf(fmaxf(rintf(f[j] * inv), -1.f), 1.f));
            if (h16) h16[i + j] = __float2half(f[j]);
        }
    }
    if (wo) *(ull*)wo = *(ull*)q8;
}

// ---------------- per-token absmax quantization -> int8 (warp per row) ----------------
__global__ void quant_act_i8(const float* __restrict__ x, int8_t* __restrict__ xq,
                             float* __restrict__ rows) {
    int w = (blockIdx.x * blockDim.x + threadIdx.x) >> 5;  // one warp per row
    int lane = threadIdx.x & 31;
    const float* xr = x + (size_t)w * Eq;
    float4 v[16];
    float mx = 0.f;
#pragma unroll
    for (int i = 0; i < 16; i++) {
        v[i] = *(const float4*)&xr[i * 128 + lane * 4];
        mx = fmaxf(mx, fmaxf(fmaxf(fabsf(v[i].x), fabsf(v[i].y)),
                             fmaxf(fabsf(v[i].z), fabsf(v[i].w))));
    }
#pragma unroll
    for (int o = 16; o > 0; o >>= 1) mx = fmaxf(mx, __shfl_xor_sync(0xffffffffu, mx, o));
    float s = __fdiv_rn(127.0f, fmaxf(mx, 1e-5f));
    if (lane == 0) rows[w] = s;
    int8_t* xo = xq + (size_t)w * Eq;
#pragma unroll
    for (int i = 0; i < 16; i++) {
        int8_t c4[4];
        c4[0] = (int8_t)(int)fminf(fmaxf(rintf(v[i].x * s), -128.f), 127.f);
        c4[1] = (int8_t)(int)fminf(fmaxf(rintf(v[i].y * s), -128.f), 127.f);
        c4[2] = (int8_t)(int)fminf(fmaxf(rintf(v[i].z * s), -128.f), 127.f);
        c4[3] = (int8_t)(int)fminf(fmaxf(rintf(v[i].w * s), -128.f), 127.f);
        *(uint32_t*)&xo[i * 128 + lane * 4] = *(uint32_t*)c4;
    }
}

// ---------------- fp32 -> fp16 copy (reasoning tokens) ----------------
__global__ void to_fp16(const float* __restrict__ X, __half* __restrict__ Y) {
    size_t i = ((size_t)blockIdx.x * 256 + threadIdx.x) * 4;
    float4 v = *(const float4*)&X[i];
    *(uint32_t*)&Y[i] = h2pack(v.x, v.y);
    *(uint32_t*)&Y[i + 2] = h2pack(v.z, v.w);
}

// ---------------- IMMA int8 GEMM: QKV projections, exact, fp16 out ----------------
// A[m, K] int8 row-major (K bytes/row), B[n, K] int8. C = (A.B^T) * cmul*ws/rows[m] -> fp16.
// Tile 128x128, k-slice 128 int8 (= 128 bytes = same smem geometry as bf16 path).
struct IArgs {
    const int8_t* B;
    const float* wsp;
    __half* Hout;
    int rbo;
    float cmul;
};

#define SMEM_GEMM5 98304   // 3 stages x (A 16K | B 16K)

__global__ __launch_bounds__(256, 2) void imma_gemm(const int8_t* __restrict__ A,
                                                    const float* __restrict__ rowscale,
                                                    IArgs ia0, IArgs ia1, IArgs ia2) {
    int z = blockIdx.z;
    IArgs ia = (z == 0) ? ia0 : ((z == 1) ? ia1 : ia2);
    extern __shared__ __align__(128) uint8_t dsm[];
    uint32_t sb = smem_u32(dsm);
    int t = threadIdx.x;
    int lane = t & 31, wid = t >> 5;
    int m0 = blockIdx.y * 128, n0 = blockIdx.x * 128;
    int warp_m = wid & 1, warp_n = wid >> 1;
    const int K = Eq;   // bytes per row

    const uint8_t* asrc[4];
    const uint8_t* bsrc[4];
    uint32_t gdst[4];
#pragma unroll
    for (int i = 0; i < 4; i++) {
        int idx = t + i * 256;
        int r = idx >> 3, g = idx & 7;
        gdst[i] = (g >> 2) * 8192 + swoff(r, g & 3);
        asrc[i] = (const uint8_t*)(A + (size_t)(m0 + r) * K) + g * 16;
        bsrc[i] = (const uint8_t*)(ia.B + (size_t)(n0 + r) * K) + g * 16;
    }

    uint32_t aaddr[4], baddr4[2];
#pragma unroll
    for (int mi = 0; mi < 4; mi++)
        aaddr[mi] = swoff(warp_m * 64 + mi * 16 + (lane & 15), lane >> 4);
#pragma unroll
    for (int ni2 = 0; ni2 < 2; ni2++)
        baddr4[ni2] = boff4(warp_n * 32 + ni2 * 16, lane);

    const int NK = K >> 7;   // 128 int8 per k-slice
    {
#pragma unroll
        for (int i = 0; i < 4; i++) {
            cpa16(sb + gdst[i], asrc[i]);
            cpa16(sb + 16384 + gdst[i], bsrc[i]);
        }
        cpa_commit();
    }

    int c[4][4][4];
#pragma unroll
    for (int mi = 0; mi < 4; mi++)
#pragma unroll
        for (int ni = 0; ni < 4; ni++)
#pragma unroll
            for (int k = 0; k < 4; k++) c[mi][ni][k] = 0;

    int s = 0;
    for (int kt = 0; kt < NK; ++kt) {
        if (kt + 1 < NK) {
            int sn = (s + 1 == 3) ? 0 : s + 1;
            uint32_t base = sb + sn * 32768;
            size_t koff = (size_t)(kt + 1) * 128;
#pragma unroll
            for (int i = 0; i < 4; i++) {
                cpa16(base + gdst[i], asrc[i] + koff);
                cpa16(base + 16384 + gdst[i], bsrc[i] + koff);
            }
            cpa_commit();
            cpa_wait1();
        } else {
            cpa_wait0();
        }
        __syncthreads();

        uint32_t Ab = sb + s * 32768;
        uint32_t Bb = Ab + 16384;
#pragma unroll
        for (int ch = 0; ch < 2; ch++)
#pragma unroll
            for (int ks = 0; ks < 2; ks++) {
                uint32_t kx = ks * 32;
                uint32_t a[4][4], b[2][4];
#pragma unroll
                for (int mi = 0; mi < 4; mi++)
                    ldmx4(a[mi], Ab + ch * 8192 + (aaddr[mi] ^ kx));
#pragma unroll
                for (int ni2 = 0; ni2 < 2; ni2++)
                    ldmx4(b[ni2], Bb + ch * 8192 + (baddr4[ni2] ^ kx));
#pragma unroll
                for (int mi = 0; mi < 4; mi++)
#pragma unroll
                    for (int ni = 0; ni < 4; ni++)
                        mma16832s8(c[mi][ni], a[mi], &b[ni >> 1][(ni & 1) * 2]);
            }
        s = (s + 1 == 3) ? 0 : s + 1;
    }

    float ws = ia.cmul * (*ia.wsp);
    int g = lane >> 2, tg = lane & 3;
#pragma unroll
    for (int mi = 0; mi < 4; mi++) {
        int mA = m0 + warp_m * 64 + mi * 16 + g;
        int mB = mA + 8;
        float fA = ws / rowscale[mA];
        float fB = ws / rowscale[mB];
        int oA = (mA / Sq) * ia.rbo + (mA % Sq);
        int oB = (mB / Sq) * ia.rbo + (mB % Sq);
        __half* hA = ia.Hout + (size_t)oA * Eq;
        __half* hB = ia.Hout + (size_t)oB * Eq;
#pragma unroll
        for (int ni = 0; ni < 4; ni++) {
            int col = n0 + warp_n * 32 + ni * 8 + tg * 2;
            *(uint32_t*)&hA[col] = h2pack((float)c[mi][ni][0] * fA, (float)c[mi][ni][1] * fA);
            *(uint32_t*)&hB[col] = h2pack((float)c[mi][ni][2] * fB, (float)c[mi][ni][3] * fB);
        }
    }
}

// ---------------- HMMA fp16 GEMM (reasoning + out-proj) ----------------
struct GArgs {
    const __half* A;
    const __half* B;
    float* C;
    const float* bias;
    int K, Nout, rbi, rbo, roff, ylim;
    __half* Hout;
};

__global__ __launch_bounds__(256, 2) void hmma_gemm6(GArgs ga0, GArgs ga1) {
    GArgs ga = (blockIdx.z == 0) ? ga0 : ga1;
    if ((int)blockIdx.y >= ga.ylim) return;
    extern __shared__ __align__(128) uint8_t dsm[];
    uint32_t sb = smem_u32(dsm);
    int t = threadIdx.x;
    int lane = t & 31, wid = t >> 5;
    int m0 = blockIdx.y * 128, n0 = blockIdx.x * 128;
    int warp_m = wid & 1, warp_n = wid >> 1;
    const int K = ga.K;

    const uint8_t* asrc[4];
    const uint8_t* bsrc[4];
    uint32_t gdst[4];
#pragma unroll
    for (int i = 0; i < 4; i++) {
        int idx = t + i * 256;
        int r = idx >> 3, g = idx & 7;
        gdst[i] = (g >> 2) * 8192 + swoff(r, g & 3);
        asrc[i] = (const uint8_t*)(ga.A + (size_t)(m0 + r) * K) + g * 16;
        bsrc[i] = (const uint8_t*)(ga.B + (size_t)(n0 + r) * K) + g * 16;
    }

    uint32_t aaddr[4], baddr4[2];
#pragma unroll
    for (int mi = 0; mi < 4; mi++)
        aaddr[mi] = swoff(warp_m * 64 + mi * 16 + (lane & 15), lane >> 4);
#pragma unroll
    for (int ni2 = 0; ni2 < 2; ni2++)
        baddr4[ni2] = boff4(warp_n * 32 + ni2 * 16, lane);

    const int NK = K >> 6;
    {
#pragma unroll
        for (int i = 0; i < 4; i++) {
            cpa16(sb + gdst[i], asrc[i]);
            cpa16(sb + 16384 + gdst[i], bsrc[i]);
        }
        cpa_commit();
    }

    float c[4][4][4];
#pragma unroll
    for (int mi = 0; mi < 4; mi++)
#pragma unroll
        for (int ni = 0; ni < 4; ni++)
#pragma unroll
            for (int k = 0; k < 4; k++) c[mi][ni][k] = 0.f;

    int s = 0;
    for (int kt = 0; kt < NK; ++kt) {
        if (kt + 1 < NK) {
            int sn = (s + 1 == 3) ? 0 : s + 1;
            uint32_t base = sb + sn * 32768;
            size_t koff = (size_t)(kt + 1) * 128;
#pragma unroll
            for (int i = 0; i < 4; i++) {
                cpa16(base + gdst[i], asrc[i] + koff);
                cpa16(base + 16384 + gdst[i], bsrc[i] + koff);
            }
            cpa_commit();
            cpa_wait1();
        } else {
            cpa_wait0();
        }
        __syncthreads();

        uint32_t Ab = sb + s * 32768;
        uint32_t Bb = Ab + 16384;
#pragma unroll
        for (int ch = 0; ch < 2; ch++)
#pragma unroll
            for (int ks = 0; ks < 2; ks++) {
                uint32_t kx = ks * 32;
                uint32_t a[4][4], b[2][4];
#pragma unroll
                for (int mi = 0; mi < 4; mi++)
                    ldmx4(a[mi], Ab + ch * 8192 + (aaddr[mi] ^ kx));
#pragma unroll
                for (int ni2 = 0; ni2 < 2; ni2++)
                    ldmx4(b[ni2], Bb + ch * 8192 + (baddr4[ni2] ^ kx));
#pragma unroll
                for (int mi = 0; mi < 4; mi++)
#pragma unroll
                    for (int ni = 0; ni < 4; ni++)
                        mma16816h(c[mi][ni], a[mi], &b[ni >> 1][(ni & 1) * 2]);
            }
        s = (s + 1 == 3) ? 0 : s + 1;
    }

    int g = lane >> 2, tg = lane & 3;
#pragma unroll
    for (int mi = 0; mi < 4; mi++) {
        int mA = m0 + warp_m * 64 + mi * 16 + g;
        int mB = mA + 8;
        int oA = (mA / ga.rbi) * ga.rbo + ga.roff + (mA % ga.rbi);
        int oB = (mB / ga.rbi) * ga.rbo + ga.roff + (mB % ga.rbi);
        if (ga.Hout) {
            __half* hA = ga.Hout + (size_t)oA * ga.Nout;
            __half* hB = ga.Hout + (size_t)oB * ga.Nout;
#pragma unroll
            for (int ni = 0; ni < 4; ni++) {
                int col = n0 + warp_n * 32 + ni * 8 + tg * 2;
                *(uint32_t*)&hA[col] = h2pack(c[mi][ni][0], c[mi][ni][1]);
                *(uint32_t*)&hB[col] = h2pack(c[mi][ni][2], c[mi][ni][3]);
            }
        } else {
            float* crA = ga.C + (size_t)oA * ga.Nout;
            float* crB = ga.C + (size_t)oB * ga.Nout;
#pragma unroll
            for (int ni = 0; ni < 4; ni++) {
                int col = n0 + warp_n * 32 + ni * 8 + tg * 2;
                float b0 = ga.bias ? ga.bias[col] : 0.f;
                float b1 = ga.bias ? ga.bias[col + 1] : 0.f;
                float2 vA, vB;
                vA.x = c[mi][ni][0] + b0;
                vA.y = c[mi][ni][1] + b1;
                vB.x = c[mi][ni][2] + b0;
                vB.y = c[mi][ni][3] + b1;
                *(float2*)&crA[col] = vA;
                *(float2*)&crB[col] = vB;
            }
        }
    }
}

// ---------------- FA2 HMMA flash attention: 3 CTAs/SM, 64q/CTA, 32-key 3-stage KV ----------------
#define ATT_STAGE 16384
#define SMEM_ATTN7 (3 * ATT_STAGE)   // 49152 -> 3 CTAs/SM

__global__ __launch_bounds__(128, 3) void attn_mma6(
    const __half* __restrict__ Q16, const __half* __restrict__ K16,
    const __half* __restrict__ V16, __half* __restrict__ O16) {
    extern __shared__ char smg[];
    uint32_t sb = smem_u32(smg);
    int t = threadIdx.x;
    int lane = t & 31, wid = t >> 5;   // 4 warps
    int qb = blockIdx.x * 64;
    int h = blockIdx.y;
    int b = blockIdx.z;

    const int wm = wid;
    const uint32_t a_off = swoff(wm * 16 + (lane & 15), lane >> 4);
    uint32_t k4[2];
#pragma unroll
    for (int ni2 = 0; ni2 < 2; ni2++) k4[ni2] = boff4(ni2 * 16, lane);
    const int vrow = (lane & 7) + ((lane >> 3) & 1) * 8;
    const uint32_t vbase = (uint32_t)(vrow * 64);
    const uint32_t vrx = (uint32_t)((vrow >> 1) & 3);
    const uint32_t vg = (uint32_t)((lane >> 4) & 1);
    const uint32_t ge = ((vg ^ vrx) << 4);
    const uint32_t go = (((2 + vg) ^ vrx) << 4);
    const int g4 = lane >> 2, tg = lane & 3;

    // ---- stage Q at sb+0, consume to regs, then start ring ----
    {
        const __half* Qg = Q16 + ((size_t)(b * Sq + qb)) * Eq + h * Dq;
#pragma unroll
        for (int i = 0; i < 8; i++) {
            int idx = t + i * 128;
            int r = idx >> 4, g = idx & 15;
            uint32_t dst = (g >> 2) * 4096 + swoff(r, g & 3);
            cpa16(sb + dst, Qg + (size_t)r * Eq + g * 8);
        }
        cpa_commit();
    }
    cpa_wait0();
    __syncthreads();

    uint32_t qf[4][2][4];
#pragma unroll
    for (int ch = 0; ch < 4; ch++)
#pragma unroll
        for (int ks = 0; ks < 2; ks++)
            ldmx4(qf[ch][ks], sb + ch * 4096 + (a_off ^ (ks * 32)));
    __syncthreads();

    const __half* Kb = K16 + ((size_t)(b * Lq)) * Eq + h * Dq;
    const __half* Vb = V16 + ((size_t)(b * Lq)) * Eq + h * Dq;

    auto issueKV = [&](int kt) {
        uint32_t base = sb + (kt % 3) * ATT_STAGE;
        const __half* KT = Kb + (size_t)(kt * 32) * Eq;
        const __half* VT = Vb + (size_t)(kt * 32) * Eq;
#pragma unroll
        for (int i = 0; i < 4; i++) {
            int idx = t + i * 128;
            int r = idx >> 4, g = idx & 15;
            uint32_t dst = (g >> 2) * 2048 + swoff(r, g & 3);
            size_t src = (size_t)r * Eq + g * 8;
            cpa16(base + dst, KT + src);
            cpa16(base + 8192 + dst, VT + src);
        }
        cpa_commit();
    };
    issueKV(0);

    float m0 = -1e30f, m1 = -1e30f, l0 = 0.f, l1 = 0.f;
    float co[16][4];
#pragma unroll
    for (int i = 0; i < 16; i++)
#pragma unroll
        for (int j = 0; j < 4; j++) co[i][j] = 0.f;

    const int NT = Lq / 32;  // 68
    for (int kt = 0; kt < NT; ++kt) {
        if (kt + 1 < NT) { issueKV(kt + 1); cpa_wait1(); }
        else cpa_wait0();
        __syncthreads();
        uint32_t kvb = sb + (kt % 3) * ATT_STAGE;

        // ---- S = Q.K (fp16) ----
        float cs[4][4];
#pragma unroll
        for (int i = 0; i < 4; i++)
#pragma unroll
            for (int j = 0; j < 4; j++) cs[i][j] = 0.f;
#pragma unroll
        for (int ch = 0; ch < 4; ch++)
#pragma unroll
            for (int ks = 0; ks < 2; ks++) {
                uint32_t kx = ks * 32;
#pragma unroll
                for (int ni2 = 0; ni2 < 2; ni2++) {
                    uint32_t bk[4];
                    ldmx4(bk, kvb + ch * 2048 + (k4[ni2] ^ kx));
                    mma16816h(cs[2 * ni2], qf[ch][ks], bk);
                    mma16816h(cs[2 * ni2 + 1], qf[ch][ks], bk + 2);
                }
            }

        // ---- in-register softmax (32 keys) ----
        float tm0 = -1e30f, tm1 = -1e30f;
#pragma unroll
        for (int ni = 0; ni < 4; ni++) {
            tm0 = fmaxf(tm0, fmaxf(cs[ni][0], cs[ni][1]));
            tm1 = fmaxf(tm1, fmaxf(cs[ni][2], cs[ni][3]));
        }
        tm0 = fmaxf(tm0, __shfl_xor_sync(0xffffffffu, tm0, 1));
        tm0 = fmaxf(tm0, __shfl_xor_sync(0xffffffffu, tm0, 2));
        tm1 = fmaxf(tm1, __shfl_xor_sync(0xffffffffu, tm1, 1));
        tm1 = fmaxf(tm1, __shfl_xor_sync(0xffffffffu, tm1, 2));
        float nm0 = fmaxf(m0, tm0), nm1 = fmaxf(m1, tm1);
        float al0 = __expf(m0 - nm0), al1 = __expf(m1 - nm1);
        m0 = nm0; m1 = nm1;

        float rs0 = 0.f, rs1 = 0.f;
#pragma unroll
        for (int ni = 0; ni < 4; ni++) {
            cs[ni][0] = __expf(cs[ni][0] - m0); rs0 += cs[ni][0];
            cs[ni][1] = __expf(cs[ni][1] - m0); rs0 += cs[ni][1];
            cs[ni][2] = __expf(cs[ni][2] - m1); rs1 += cs[ni][2];
            cs[ni][3] = __expf(cs[ni][3] - m1); rs1 += cs[ni][3];
        }
        rs0 += __shfl_xor_sync(0xffffffffu, rs0, 1);
        rs0 += __shfl_xor_sync(0xffffffffu, rs0, 2);
        rs1 += __shfl_xor_sync(0xffffffffu, rs1, 1);
        rs1 += __shfl_xor_sync(0xffffffffu, rs1, 2);
        l0 = l0 * al0 + rs0;
        l1 = l1 * al1 + rs1;

        // ---- P fp16 A-fragments ----
        uint32_t pf[2][4];
#pragma unroll
        for (int ck = 0; ck < 2; ck++) {
            pf[ck][0] = h2pack(cs[2 * ck][0], cs[2 * ck][1]);
            pf[ck][1] = h2pack(cs[2 * ck][2], cs[2 * ck][3]);
            pf[ck][2] = h2pack(cs[2 * ck + 1][0], cs[2 * ck + 1][1]);
            pf[ck][3] = h2pack(cs[2 * ck + 1][2], cs[2 * ck + 1][3]);
        }

        // ---- rescale O ----
#pragma unroll
        for (int ni = 0; ni < 16; ni++) {
            co[ni][0] *= al0; co[ni][1] *= al0;
            co[ni][2] *= al1; co[ni][3] *= al1;
        }

        // ---- O += P.V (fp16, trans-loaded V) ----
#pragma unroll
        for (int ck = 0; ck < 2; ck++) {
            uint32_t rofs = kvb + 8192 + (uint32_t)(ck * 1024) + vbase;
#pragma unroll
            for (int ni2 = 0; ni2 < 8; ni2++) {
                uint32_t bv[4];
                ldmx4t(bv, rofs + (uint32_t)((ni2 >> 1) * 2048) + ((ni2 & 1) ? go : ge));
                mma16816h(co[2 * ni2], pf[ck], bv);
                mma16816h(co[2 * ni2 + 1], pf[ck], bv + 2);
            }
        }
    }

    // ---- epilogue: write O fp16 ----
    float il0 = 1.0f / l0, il1 = 1.0f / l1;
    int r0 = wm * 16 + g4, r1 = r0 + 8;
    __half* O0 = O16 + ((size_t)(b * Sq + qb + r0)) * Eq + h * Dq;
    __half* O1 = O16 + ((size_t)(b * Sq + qb + r1)) * Eq + h * Dq;
#pragma unroll
    for (int ni = 0; ni < 16; ni++) {
        int col = ni * 8 + tg * 2;
        *(uint32_t*)(O0 + col) = h2pack(co[ni][0] * il0, co[ni][1] * il0);
        *(uint32_t*)(O1 + col) = h2pack(co[ni][2] * il1, co[ni][3] * il1);
    }
}

// ---------------- host launcher ----------------
extern "C" void kernel_launch(void* const* d_in, const int* in_sizes, int n_in,
                              void* d_out, int out_size) {
    const float* x  = (const float*)d_in[0];
    const float* rt = (const float*)d_in[1];
    const float* qw = (const float*)d_in[2];
    const float* kw = (const float*)d_in[3];
    const float* vw = (const float*)d_in[4];
    const float* ow = (const float*)d_in[5];
    const float* ob = (const float*)d_in[6];
    float* out = (float*)d_out;

    int8_t *x8, *w8;
    __half *rt16, *kw16, *vw16, *ow16, *o16, *q16, *k16, *v16;
    float *rows, *part, *scale;
    cudaGetSymbolAddress((void**)&x8, g_x8);
    cudaGetSymbolAddress((void**)&w8, g_w8);
    cudaGetSymbolAddress((void**)&rt16, g_rt16);
    cudaGetSymbolAddress((void**)&kw16, g_kw16);
    cudaGetSymbolAddress((void**)&vw16, g_vw16);
    cudaGetSymbolAddress((void**)&ow16, g_ow16);
    cudaGetSymbolAddress((void**)&o16, g_o16);
    cudaGetSymbolAddress((void**)&q16, g_q16);
    cudaGetSymbolAddress((void**)&k16, g_k16);
    cudaGetSymbolAddress((void**)&v16, g_v16);
    cudaGetSymbolAddress((void**)&rows, g_rows);
    cudaGetSymbolAddress((void**)&part, g_part);
    cudaGetSymbolAddress((void**)&scale, g_scale);

    cudaFuncSetAttribute(attn_mma6, cudaFuncAttributeMaxDynamicSharedMemorySize, SMEM_ATTN7);
    cudaFuncSetAttribute(hmma_gemm6, cudaFuncAttributeMaxDynamicSharedMemorySize, SMEM_GEMM5);
    cudaFuncSetAttribute(imma_gemm, cudaFuncAttributeMaxDynamicSharedMemorySize, SMEM_GEMM5);

    const float SCALE = 0.08838834764831845f;  // 1/sqrt(128), folded into Q epilogue

    // 1) weight scales
    reduce_abs_kernel<<<dim3(1024, 3), 256>>>(qw, kw, vw, part);
    finalize_scale_kernel<<<3, 256>>>(part, scale);
    // 2) weight prep (ternary int8 q/k/v + kw16/vw16/ow16 fp16) + act quant int8 + rt fp16
    prep_weights<<<dim3(2048, 4), 256>>>(qw, kw, vw, ow, w8, kw16, vw16, ow16, scale);
    quant_act_i8<<<(Bq * Sq) / 8, 256>>>(x, x8, rows);
    to_fp16<<<(Bq * Rq * Eq) / 1024, 256>>>(rt, rt16);
    // 3) QKV projections: exact int8 IMMA (z = 0..2), fp16 out
    size_t EE = (size_t)Eq * Eq;
    IArgs iQ = { w8 + 0 * EE, scale + 0, q16, Sq, SCALE };
    IArgs iK = { w8 + 1 * EE, scale + 1, k16, Lq, 1.0f };
    IArgs iV = { w8 + 2 * EE, scale + 2, v16, Lq, 1.0f };
    imma_gemm<<<dim3(16, 32, 3), 256, SMEM_GEMM5>>>(x8, rows, iQ, iK, iV);
    // 4) reasoning projections (fp16, K=2048), appended after S self rows
    GArgs gRK = { rt16, kw16, nullptr, nullptr, Eq, Eq, Rq, Lq, Sq, 2, k16 };
    GArgs gRV = { rt16, vw16, nullptr, nullptr, Eq, Eq, Rq, Lq, Sq, 2, v16 };
    hmma_gemm6<<<dim3(16, 2, 2), 256, SMEM_GEMM5>>>(gRK, gRV);
    // 5) attention (3 CTAs/SM, fp16 QK + fp16 PV) -> fp16 O
    attn_mma6<<<dim3(Sq / 64, Hq, Bq), 128, SMEM_ATTN7>>>(q16, k16, v16, o16);
    // 6) output projection + bias (fp16, K=2048)
    GArgs gO = { o16, ow16, out, ob, Eq, Eq, Bq * Sq, Bq * Sq, 0, 32, nullptr };
    hmma_gemm6<<<dim3(16, 32, 1), 256, SMEM_GEMM5>>>(gO, gO);
}